// round 1
// baseline (speedup 1.0000x reference)
#include <cuda_runtime.h>
#include <math.h>

// Problem dims (fixed by the dataset)
#define NR 4096      // B*T
#define DY 784
#define DH 400
#define KS 16        // HMM states
#define LD 16        // latent dim
#define BBAT 32
#define TT 128

// ---------------- scratch (__device__ globals; no allocation allowed) -------
__device__ float g_yT[DY * NR];       // y transposed   [784][4096]
__device__ float g_w1T[DY * DH];      // enc_w1^T       [784][400]
__device__ float g_h[NR * DH];        // encoder hidden [4096][400]
__device__ float g_z[NR * LD];        // latent z       [4096][16]
__device__ float g_baseT[DH * NR];    // base K-major   [400][4096]
__device__ float g_dwT[DH * DY];      // dec_w^T        [400][784]
__device__ float g_logb[NR * KS];     // log b_k(y_t)   [4096][16]

// ---------------- generic 32x32 transpose ----------------------------------
__global__ void transpose_kernel(const float* __restrict__ src, int M, int N, int which) {
    float* dst = (which == 0) ? g_yT : (which == 1) ? g_w1T : g_dwT;
    __shared__ float tile[32][33];
    int bx = blockIdx.x * 32, by = blockIdx.y * 32;
    int x = bx + threadIdx.x;
#pragma unroll
    for (int i = 0; i < 32; i += 8) {
        int y = by + threadIdx.y + i;
        if (x < N && y < M) tile[threadIdx.y + i][threadIdx.x] = src[(long)y * N + x];
    }
    __syncthreads();
    int x2 = by + threadIdx.x;
#pragma unroll
    for (int i = 0; i < 32; i += 8) {
        int y2 = bx + threadIdx.y + i;
        if (x2 < M && y2 < N) dst[(long)y2 * M + x2] = tile[threadIdx.x][threadIdx.y + i];
    }
}

// ---------------- enc GEMM1: h = relu(y @ W1^T + b1) ------------------------
// C[4096][400], K=784. 64x64 tile, 256 threads, 4x4 register tile.
__global__ void gemm1_kernel(const float* __restrict__ b1) {
    __shared__ float sA[8][64];
    __shared__ float sB[8][64];
    int n0 = blockIdx.x * 64, c0 = blockIdx.y * 64;
    int tid = threadIdx.x;
    int tx = tid & 15, ty = tid >> 4;
    int la_k = tid >> 5;          // 0..7
    int la_m = (tid * 2) & 63;    // even
    float acc[4][4];
#pragma unroll
    for (int r = 0; r < 4; r++)
#pragma unroll
        for (int c = 0; c < 4; c++) acc[r][c] = 0.f;

    for (int kk = 0; kk < DY; kk += 8) {
        float2 av = *(const float2*)&g_yT[(kk + la_k) * NR + n0 + la_m];
        sA[la_k][la_m] = av.x;
        sA[la_k][la_m + 1] = av.y;
        int cc = c0 + la_m;
        sB[la_k][la_m]     = (cc     < DH) ? g_w1T[(kk + la_k) * DH + cc]     : 0.f;
        sB[la_k][la_m + 1] = (cc + 1 < DH) ? g_w1T[(kk + la_k) * DH + cc + 1] : 0.f;
        __syncthreads();
#pragma unroll
        for (int i = 0; i < 8; i++) {
            float4 a4 = *(const float4*)&sA[i][ty * 4];
            float4 b4 = *(const float4*)&sB[i][tx * 4];
            float a[4] = {a4.x, a4.y, a4.z, a4.w};
            float b[4] = {b4.x, b4.y, b4.z, b4.w};
#pragma unroll
            for (int r = 0; r < 4; r++)
#pragma unroll
                for (int c = 0; c < 4; c++) acc[r][c] = fmaf(a[r], b[c], acc[r][c]);
        }
        __syncthreads();
    }
#pragma unroll
    for (int r = 0; r < 4; r++) {
        int n = n0 + ty * 4 + r;
#pragma unroll
        for (int c = 0; c < 4; c++) {
            int h = c0 + tx * 4 + c;
            if (h < DH) g_h[n * DH + h] = fmaxf(acc[r][c] + b1[h], 0.f);
        }
    }
}

// ---------------- enc GEMM2 + reparameterization ----------------------------
// ml = h @ W2^T + b2 (4096x32, K=400); z = mu + eps*exp(0.5*logvar)
__global__ void enc2_kernel(const float* __restrict__ w2, const float* __restrict__ b2,
                            const float* __restrict__ eps) {
    __shared__ float sh_h[16][401];
    __shared__ float sw[32][65];
    __shared__ float sml[16][32];
    int n0 = blockIdx.x * 16;
    int tid = threadIdx.x;
    for (int e = tid; e < 16 * DH; e += 256) {
        int r = e / DH, l = e % DH;
        sh_h[r][l] = g_h[(n0 + r) * DH + l];
    }
    int r0 = tid >> 5, jj = tid & 31;
    float a0 = b2[jj], a1 = b2[jj];
    for (int l0 = 0; l0 < DH; l0 += 64) {
        int w = min(64, DH - l0);
        for (int e = tid; e < 32 * 64; e += 256) {
            int j = e >> 6, ll = e & 63;
            if (ll < w) sw[j][ll] = w2[j * DH + l0 + ll];
        }
        __syncthreads();
        for (int ll = 0; ll < w; ll++) {
            float wv = sw[jj][ll];
            a0 = fmaf(sh_h[r0][l0 + ll], wv, a0);
            a1 = fmaf(sh_h[r0 + 8][l0 + ll], wv, a1);
        }
        __syncthreads();
    }
    sml[r0][jj] = a0;
    sml[r0 + 8][jj] = a1;
    __syncthreads();
    {
        int r = tid >> 4, l = tid & 15;
        float mu = sml[r][l], lv = sml[r][16 + l];
        g_z[(n0 + r) * LD + l] = fmaf(eps[(n0 + r) * LD + l], expf(0.5f * lv), mu);
    }
}

// ---------------- base^T[h][n] = dec_fc_b[h] + z[n] . Wz[h] -----------------
__global__ void dec_base_kernel(const float* __restrict__ dec_fc_w,
                                const float* __restrict__ dec_fc_b) {
    int idx = blockIdx.x * 256 + threadIdx.x;   // 400*4096 total
    int h = idx >> 12;
    int n = idx & 4095;
    float acc = dec_fc_b[h];
    const float* wrow = dec_fc_w + h * 32;      // cols 0..15 = Wz
    const float4* zp = (const float4*)&g_z[n * LD];
#pragma unroll
    for (int q = 0; q < 4; q++) {
        float4 zv = zp[q];
        acc = fmaf(zv.x, wrow[4 * q + 0], acc);
        acc = fmaf(zv.y, wrow[4 * q + 1], acc);
        acc = fmaf(zv.z, wrow[4 * q + 2], acc);
        acc = fmaf(zv.w, wrow[4 * q + 3], acc);
    }
    g_baseT[idx] = acc;
}

// ---------------- fused big GEMM + BCE reduce --------------------------------
// For component k, row tile of 64 n's: S = relu(base + Wx_k) @ dec_w^T,
// BCE against y, reduce over 784 outputs -> g_logb[n][k] = -recon/100.
// grid (64, 16), 256 threads, 64x64 S tiles looped over o.
__global__ void bk_kernel(const float* __restrict__ dec_fc_w,
                          const float* __restrict__ dec_b,
                          const float* __restrict__ y_flat) {
    __shared__ float sA[8][64];
    __shared__ float sB[8][64];
    __shared__ float swx[DH];
    int k = blockIdx.y;
    int n0 = blockIdx.x * 64;
    int tid = threadIdx.x;
    for (int i = tid; i < DH; i += 256) swx[i] = dec_fc_w[i * 32 + LD + k];
    __syncthreads();
    int tx = tid & 15, ty = tid >> 4;
    int la_k = tid >> 5, la_m = (tid * 2) & 63;
    float rec[4] = {0.f, 0.f, 0.f, 0.f};

    for (int o0 = 0; o0 < DY; o0 += 64) {
        float acc[4][4];
#pragma unroll
        for (int r = 0; r < 4; r++)
#pragma unroll
            for (int c = 0; c < 4; c++) acc[r][c] = 0.f;

        for (int kk = 0; kk < DH; kk += 8) {
            float wxa = swx[kk + la_k];
            float2 bv = *(const float2*)&g_baseT[(kk + la_k) * NR + n0 + la_m];
            sA[la_k][la_m]     = fmaxf(bv.x + wxa, 0.f);
            sA[la_k][la_m + 1] = fmaxf(bv.y + wxa, 0.f);
            int c = o0 + la_m;
            sB[la_k][la_m]     = (c     < DY) ? g_dwT[(kk + la_k) * DY + c]     : 0.f;
            sB[la_k][la_m + 1] = (c + 1 < DY) ? g_dwT[(kk + la_k) * DY + c + 1] : 0.f;
            __syncthreads();
#pragma unroll
            for (int i = 0; i < 8; i++) {
                float4 a4 = *(const float4*)&sA[i][ty * 4];
                float4 b4 = *(const float4*)&sB[i][tx * 4];
                float a[4] = {a4.x, a4.y, a4.z, a4.w};
                float b[4] = {b4.x, b4.y, b4.z, b4.w};
#pragma unroll
                for (int r = 0; r < 4; r++)
#pragma unroll
                    for (int c2 = 0; c2 < 4; c2++) acc[r][c2] = fmaf(a[r], b[c2], acc[r][c2]);
            }
            __syncthreads();
        }
        // epilogue: BCE against y, accumulate per-row partial
#pragma unroll
        for (int r = 0; r < 4; r++) {
            int n = n0 + ty * 4 + r;
            const float* yr = y_flat + (long)n * DY;
            float part = 0.f;
#pragma unroll
            for (int c = 0; c < 4; c++) {
                int o = o0 + tx * 4 + c;
                if (o < DY) {
                    float s = acc[r][c] + dec_b[o];
                    float lp, l1;
                    if (s > 0.f) { lp = -log1pf(expf(-s)); l1 = lp - s; }
                    else         { l1 = -log1pf(expf(s));  lp = l1 + s; }
                    lp = fmaxf(lp, -100.f);
                    l1 = fmaxf(l1, -100.f);
                    float yv = yr[o];
                    part -= yv * lp + (1.f - yv) * l1;
                }
            }
            rec[r] += part;
        }
    }
    // reduce over the 16 column-threads (width-16 shuffle groups)
#pragma unroll
    for (int r = 0; r < 4; r++) {
        float v = rec[r];
#pragma unroll
        for (int off = 8; off > 0; off >>= 1) v += __shfl_down_sync(0xffffffffu, v, off, 16);
        if (tx == 0) g_logb[(n0 + ty * 4 + r) * KS + k] = -v * 0.01f;
    }
}

// ---------------- HMM forward-backward + gamma/xi ----------------------------
__global__ void hmm_kernel(const float* __restrict__ log_pi, const float* __restrict__ log_A,
                           float* __restrict__ out) {
    __shared__ float lA[16][17];
    __shared__ float lp[16];
    __shared__ float lb[TT][16];
    __shared__ float al[TT][16];
    __shared__ float be[TT][16];
    __shared__ float s_llik;
    int b = blockIdx.x;
    int tid = threadIdx.x;

    for (int e = tid; e < TT * 16; e += 256) ((float*)lb)[e] = g_logb[b * (TT * 16) + e];

    if (tid < 16) {
        int j = tid;
        float x[16], m = -1e30f;
#pragma unroll
        for (int k2 = 0; k2 < 16; k2++) { x[k2] = log_A[j * 16 + k2]; m = fmaxf(m, x[k2]); }
        float s = 0.f;
#pragma unroll
        for (int k2 = 0; k2 < 16; k2++) s += expf(x[k2] - m);
        float inv = 1.f / s;
#pragma unroll
        for (int k2 = 0; k2 < 16; k2++) lA[j][k2] = logf(expf(x[k2] - m) * inv + 1e-9f);
    } else if (tid == 16) {
        float x[16], m = -1e30f;
#pragma unroll
        for (int k2 = 0; k2 < 16; k2++) { x[k2] = log_pi[k2]; m = fmaxf(m, x[k2]); }
        float s = 0.f;
#pragma unroll
        for (int k2 = 0; k2 < 16; k2++) s += expf(x[k2] - m);
        float inv = 1.f / s;
#pragma unroll
        for (int k2 = 0; k2 < 16; k2++) lp[k2] = logf(expf(x[k2] - m) * inv + 1e-9f);
    }
    __syncthreads();

    int warp = tid >> 5, lane = tid & 31;
    if (warp == 0 && lane < 16) {
        // forward
        int k = lane;
        al[0][k] = lp[k] + lb[0][k];
        __syncwarp(0xffffu);
        for (int t = 1; t < TT; t++) {
            float m = -1e30f;
#pragma unroll
            for (int j = 0; j < 16; j++) m = fmaxf(m, al[t - 1][j] + lA[j][k]);
            float s = 0.f;
#pragma unroll
            for (int j = 0; j < 16; j++) s += expf(al[t - 1][j] + lA[j][k] - m);
            al[t][k] = m + logf(s) + lb[t][k];
            __syncwarp(0xffffu);
        }
        // log-likelihood = lse_k alpha[T-1][k]  (also the xi/gamma normalizer)
        float v = al[TT - 1][k];
        float mm = v;
#pragma unroll
        for (int off = 8; off > 0; off >>= 1) mm = fmaxf(mm, __shfl_xor_sync(0xffffu, mm, off, 16));
        float se = expf(v - mm);
#pragma unroll
        for (int off = 8; off > 0; off >>= 1) se += __shfl_xor_sync(0xffffu, se, off, 16);
        if (k == 0) s_llik = mm + logf(se);
    } else if (warp == 1 && lane < 16) {
        // backward (runs concurrently with forward)
        int j = lane;
        be[TT - 1][j] = 0.f;
        __syncwarp(0xffffu);
        for (int t = TT - 2; t >= 0; t--) {
            float m = -1e30f;
#pragma unroll
            for (int k2 = 0; k2 < 16; k2++)
                m = fmaxf(m, lA[j][k2] + lb[t + 1][k2] + be[t + 1][k2]);
            float s = 0.f;
#pragma unroll
            for (int k2 = 0; k2 < 16; k2++)
                s += expf(lA[j][k2] + lb[t + 1][k2] + be[t + 1][k2] - m);
            be[t][j] = m + logf(s);
            __syncwarp(0xffffu);
        }
    }
    __syncthreads();
    float llik = s_llik;

    // gamma: out[b*2048 + t*16 + k]
    float* outg = out + b * (TT * 16);
    for (int e = tid; e < TT * 16; e += 256) {
        int t = e >> 4, k = e & 15;
        outg[e] = expf(al[t][k] + be[t][k] - llik);
    }
    // xi: out[65536 + b*127*256 + t*256 + j*16 + k]
    float* outx = out + BBAT * TT * 16 + (long)b * (TT - 1) * 256;
    int j = tid >> 4, k = tid & 15;
    float lajk = lA[j][k];
    for (int t = 0; t < TT - 1; t++) {
        float v = al[t][j] + lajk + lb[t + 1][k] + be[t + 1][k] - llik;
        outx[t * 256 + tid] = expf(v);
    }
}

// ---------------- launch -----------------------------------------------------
extern "C" void kernel_launch(void* const* d_in, const int* in_sizes, int n_in,
                              void* d_out, int out_size) {
    const float* y_batch  = (const float*)d_in[0];
    const float* enc_w1   = (const float*)d_in[1];
    const float* enc_b1   = (const float*)d_in[2];
    const float* enc_w2   = (const float*)d_in[3];
    const float* enc_b2   = (const float*)d_in[4];
    const float* dec_fc_w = (const float*)d_in[5];
    const float* dec_fc_b = (const float*)d_in[6];
    const float* dec_w    = (const float*)d_in[7];
    const float* dec_b    = (const float*)d_in[8];
    const float* log_pi   = (const float*)d_in[9];
    const float* log_A    = (const float*)d_in[10];
    const float* eps      = (const float*)d_in[11];
    float* out = (float*)d_out;

    dim3 tb(32, 8);
    transpose_kernel<<<dim3((DY + 31) / 32, (NR + 31) / 32), tb>>>(y_batch, NR, DY, 0);
    transpose_kernel<<<dim3((DY + 31) / 32, (DH + 31) / 32), tb>>>(enc_w1, DH, DY, 1);
    transpose_kernel<<<dim3((DH + 31) / 32, (DY + 31) / 32), tb>>>(dec_w, DY, DH, 2);

    gemm1_kernel<<<dim3(NR / 64, (DH + 63) / 64), 256>>>(enc_b1);
    enc2_kernel<<<NR / 16, 256>>>(enc_w2, enc_b2, eps);
    dec_base_kernel<<<(DH * NR) / 256, 256>>>(dec_fc_w, dec_fc_b);
    bk_kernel<<<dim3(NR / 64, KS), 256>>>(dec_fc_w, dec_b, y_batch);
    hmm_kernel<<<BBAT, 256>>>(log_pi, log_A, out);
}

// round 5
// speedup vs baseline: 1.9777x; 1.9777x over previous
#include <cuda_runtime.h>
#include <cuda_bf16.h>
#include <math.h>
#include <stdint.h>

#define NR 4096      // B*T
#define DY 784
#define DH 400
#define KS 16        // HMM states
#define LD 16        // latent dim
#define BBAT 32
#define TT 128

// bk tiling: M=128 rows, o-chunks of 112 (x7), k-chunks of 80 (x5)
#define M_TILE 128
#define O_CH   112
#define O_CHUNKS 7
#define K_CH   80
#define KSTEPS 5          // 80/16 k-steps per chunk
#define K_CHUNKS 5

// SMEM tile pitches (bf16 elems); 88*2=176B pitch -> conflict-free ldmatrix
#define A_PITCH 88
#define B_PITCH 88

#define SB_A_HI 0
#define SB_A_LO (SB_A_HI + M_TILE * A_PITCH * 2)          // 22528
#define SB_B_HI (SB_A_LO + M_TILE * A_PITCH * 2)          // 45056
#define SB_B_LO (SB_B_HI + O_CH * B_PITCH * 2)            // 64768
#define SB_WX   (SB_B_LO + O_CH * B_PITCH * 2)            // 84480
#define SB_PART (SB_WX + 400 * 4)                         // 86080
#define SMEM_BK (SB_PART + 2 * 128 * 4)                   // 87104

// ---------------- device scratch --------------------------------------------
__device__ float g_yT[DY * NR];       // y^T [784][4096] (for gemm1)
__device__ float g_w1T[DY * DH];      // enc_w1^T
__device__ float g_h[NR * DH];        // encoder hidden
__device__ float g_z[NR * LD];        // latent z
__device__ float g_base[NR * DH];     // base [n][h] (n-major)
__device__ float g_logb[NR * KS];     // log b_k(y_t)
__device__ __align__(16) uint32_t g_Bhi[DY * 200];   // dec_w bf16-hi [784][400]
__device__ __align__(16) uint32_t g_Blo[DY * 200];   // dec_w bf16-lo

// ---------------- helpers ----------------------------------------------------
__device__ __forceinline__ uint32_t smem_u32(const void* p) {
    uint32_t a;
    asm("{ .reg .u64 t; cvta.to.shared.u64 t, %1; cvt.u32.u64 %0, t; }" : "=r"(a) : "l"(p));
    return a;
}

__device__ __forceinline__ void ldsm_x4(uint32_t* r, uint32_t addr) {
    asm volatile("ldmatrix.sync.aligned.m8n8.x4.shared.b16 {%0,%1,%2,%3}, [%4];"
                 : "=r"(r[0]), "=r"(r[1]), "=r"(r[2]), "=r"(r[3]) : "r"(addr));
}
__device__ __forceinline__ void ldsm_x2(uint32_t* r, uint32_t addr) {
    asm volatile("ldmatrix.sync.aligned.m8n8.x2.shared.b16 {%0,%1}, [%2];"
                 : "=r"(r[0]), "=r"(r[1]) : "r"(addr));
}
__device__ __forceinline__ void mma_bf16(float* c, const uint32_t* a, const uint32_t* b) {
    asm volatile("mma.sync.aligned.m16n8k16.row.col.f32.bf16.bf16.f32 "
                 "{%0,%1,%2,%3}, {%4,%5,%6,%7}, {%8,%9}, {%0,%1,%2,%3};"
                 : "+f"(c[0]), "+f"(c[1]), "+f"(c[2]), "+f"(c[3])
                 : "r"(a[0]), "r"(a[1]), "r"(a[2]), "r"(a[3]), "r"(b[0]), "r"(b[1]));
}

__device__ __forceinline__ uint32_t pack_hi_lo(float v0, float v1, uint32_t& lo_out) {
    __nv_bfloat16 h0 = __float2bfloat16(v0);
    __nv_bfloat16 h1 = __float2bfloat16(v1);
    __nv_bfloat16 l0 = __float2bfloat16(v0 - __bfloat162float(h0));
    __nv_bfloat16 l1 = __float2bfloat16(v1 - __bfloat162float(h1));
    lo_out = (uint32_t)__bfloat16_as_ushort(l0) | ((uint32_t)__bfloat16_as_ushort(l1) << 16);
    return (uint32_t)__bfloat16_as_ushort(h0) | ((uint32_t)__bfloat16_as_ushort(h1) << 16);
}

__device__ __forceinline__ float bce_term(float s, float y) {
    float l0 = -log1pf(__expf(-fabsf(s)));
    float lp = fmaxf(l0 + fminf(s, 0.f), -100.f);
    float l1 = fmaxf(l0 - fmaxf(s, 0.f), -100.f);
    return -(y * lp + (1.f - y) * l1);
}

// ---------------- generic 32x32 transpose -----------------------------------
__global__ void transpose_kernel(const float* __restrict__ src, int M, int N, int which) {
    float* dst = (which == 0) ? g_yT : g_w1T;
    __shared__ float tile[32][33];
    int bx = blockIdx.x * 32, by = blockIdx.y * 32;
    int x = bx + threadIdx.x;
#pragma unroll
    for (int i = 0; i < 32; i += 8) {
        int y = by + threadIdx.y + i;
        if (x < N && y < M) tile[threadIdx.y + i][threadIdx.x] = src[(long)y * N + x];
    }
    __syncthreads();
    int x2 = by + threadIdx.x;
#pragma unroll
    for (int i = 0; i < 32; i += 8) {
        int y2 = bx + threadIdx.y + i;
        if (x2 < M && y2 < N) dst[(long)y2 * M + x2] = tile[threadIdx.x][threadIdx.y + i];
    }
}

// ---------------- B prep: dec_w f32 -> bf16 hi/lo ---------------------------
__global__ void b_prep_kernel(const float* __restrict__ dec_w) {
    int e = blockIdx.x * 256 + threadIdx.x;  // 784*200 uint32 elems
    if (e >= DY * 200) return;
    float2 v = *(const float2*)&dec_w[e * 2];
    uint32_t lo;
    uint32_t hi = pack_hi_lo(v.x, v.y, lo);
    g_Bhi[e] = hi;
    g_Blo[e] = lo;
}

// ---------------- enc GEMM1: h = relu(y @ W1^T + b1) ------------------------
__global__ void gemm1_kernel(const float* __restrict__ b1) {
    __shared__ float sA[8][64];
    __shared__ float sB[8][64];
    int n0 = blockIdx.x * 64, c0 = blockIdx.y * 64;
    int tid = threadIdx.x;
    int tx = tid & 15, ty = tid >> 4;
    int la_k = tid >> 5;
    int la_m = (tid * 2) & 63;
    float acc[4][4];
#pragma unroll
    for (int r = 0; r < 4; r++)
#pragma unroll
        for (int c = 0; c < 4; c++) acc[r][c] = 0.f;

    for (int kk = 0; kk < DY; kk += 8) {
        float2 av = *(const float2*)&g_yT[(kk + la_k) * NR + n0 + la_m];
        sA[la_k][la_m] = av.x;
        sA[la_k][la_m + 1] = av.y;
        int cc = c0 + la_m;
        sB[la_k][la_m]     = (cc     < DH) ? g_w1T[(kk + la_k) * DH + cc]     : 0.f;
        sB[la_k][la_m + 1] = (cc + 1 < DH) ? g_w1T[(kk + la_k) * DH + cc + 1] : 0.f;
        __syncthreads();
#pragma unroll
        for (int i = 0; i < 8; i++) {
            float4 a4 = *(const float4*)&sA[i][ty * 4];
            float4 b4 = *(const float4*)&sB[i][tx * 4];
            float a[4] = {a4.x, a4.y, a4.z, a4.w};
            float b[4] = {b4.x, b4.y, b4.z, b4.w};
#pragma unroll
            for (int r = 0; r < 4; r++)
#pragma unroll
                for (int c = 0; c < 4; c++) acc[r][c] = fmaf(a[r], b[c], acc[r][c]);
        }
        __syncthreads();
    }
#pragma unroll
    for (int r = 0; r < 4; r++) {
        int n = n0 + ty * 4 + r;
#pragma unroll
        for (int c = 0; c < 4; c++) {
            int h = c0 + tx * 4 + c;
            if (h < DH) g_h[n * DH + h] = fmaxf(acc[r][c] + b1[h], 0.f);
        }
    }
}

// ---------------- enc GEMM2 + reparameterization ----------------------------
__global__ void enc2_kernel(const float* __restrict__ w2, const float* __restrict__ b2,
                            const float* __restrict__ eps) {
    __shared__ float sh_h[16][401];
    __shared__ float sw[32][65];
    __shared__ float sml[16][32];
    int n0 = blockIdx.x * 16;
    int tid = threadIdx.x;
    for (int e = tid; e < 16 * DH; e += 256) {
        int r = e / DH, l = e % DH;
        sh_h[r][l] = g_h[(n0 + r) * DH + l];
    }
    int r0 = tid >> 5, jj = tid & 31;
    float a0 = b2[jj], a1 = b2[jj];
    for (int l0 = 0; l0 < DH; l0 += 64) {
        int w = min(64, DH - l0);
        for (int e = tid; e < 32 * 64; e += 256) {
            int j = e >> 6, ll = e & 63;
            if (ll < w) sw[j][ll] = w2[j * DH + l0 + ll];
        }
        __syncthreads();
        for (int ll = 0; ll < w; ll++) {
            float wv = sw[jj][ll];
            a0 = fmaf(sh_h[r0][l0 + ll], wv, a0);
            a1 = fmaf(sh_h[r0 + 8][l0 + ll], wv, a1);
        }
        __syncthreads();
    }
    sml[r0][jj] = a0;
    sml[r0 + 8][jj] = a1;
    __syncthreads();
    {
        int r = tid >> 4, l = tid & 15;
        float mu = sml[r][l], lv = sml[r][16 + l];
        g_z[(n0 + r) * LD + l] = fmaf(eps[(n0 + r) * LD + l], expf(0.5f * lv), mu);
    }
}

// ---------------- base[n][h] = dec_fc_b[h] + z[n] . Wz[h] -------------------
__global__ void dec_base_kernel(const float* __restrict__ dec_fc_w,
                                const float* __restrict__ dec_fc_b) {
    int idx = blockIdx.x * 256 + threadIdx.x;   // NR*DH total
    int n = idx / DH;
    int h = idx - n * DH;
    float acc = dec_fc_b[h];
    const float* wrow = dec_fc_w + h * 32;
    const float4* zp = (const float4*)&g_z[n * LD];
#pragma unroll
    for (int qq = 0; qq < 4; qq++) {
        float4 zv = zp[qq];
        acc = fmaf(zv.x, wrow[4 * qq + 0], acc);
        acc = fmaf(zv.y, wrow[4 * qq + 1], acc);
        acc = fmaf(zv.z, wrow[4 * qq + 2], acc);
        acc = fmaf(zv.w, wrow[4 * qq + 3], acc);
    }
    g_base[idx] = acc;
}

// ---------------- bk kernel: bf16x3 mma.sync + fused BCE --------------------
// grid (32 m-tiles, 16 comps), 256 threads = 8 warps:
//   warp w: row-group (w&3)*32 (m32 = 2 m16-frags), col-group (w>>2)*56 (7 n8-frags)
__global__ void __launch_bounds__(256, 2)
bk_mma_kernel(const float* __restrict__ dec_fc_w,
              const float* __restrict__ dec_b,
              const float* __restrict__ y_flat) {
    extern __shared__ char smem[];
    uint32_t sb = smem_u32(smem);
    int tid = threadIdx.x;
    int w = tid >> 5, lane = tid & 31;
    int k = blockIdx.y;
    int n0 = blockIdx.x * M_TILE;
    int mw = w & 3, cg = w >> 2;
    int m0 = mw * 32;

    float* wxp = (float*)(smem + SB_WX);
    for (int i = tid; i < DH; i += 256) wxp[i] = dec_fc_w[i * 32 + LD + k];
    __syncthreads();

    // per-lane ldmatrix base addresses
    int l15 = lane & 15;
    uint32_t aAddr = sb + SB_A_HI + (uint32_t)(m0 + l15) * (A_PITCH * 2)
                     + (uint32_t)((lane >> 4) & 1) * 16;
    uint32_t bAddr = sb + SB_B_HI + (uint32_t)(cg * 56 + (l15 & 7)) * (B_PITCH * 2)
                     + (uint32_t)(l15 >> 3) * 16;

    float rec[4] = {0.f, 0.f, 0.f, 0.f};

    for (int oc = 0; oc < O_CHUNKS; oc++) {
        float acc[2][7][4];
#pragma unroll
        for (int mi = 0; mi < 2; mi++)
#pragma unroll
            for (int nf = 0; nf < 7; nf++)
#pragma unroll
                for (int c = 0; c < 4; c++) acc[mi][nf][c] = 0.f;

        for (int kc = 0; kc < K_CHUNKS; kc++) {
            // ---- build A tile: relu(base + wx) -> bf16 hi/lo, padded pitch
#pragma unroll
            for (int i = 0; i < 20; i++) {
                int e = tid + i * 256;           // 128 rows x 40 uint32
                int row = e / 40, c = e - row * 40;
                int h = kc * K_CH + 2 * c;
                float2 bv = *(const float2*)&g_base[(n0 + row) * DH + h];
                float a0 = fmaxf(bv.x + wxp[h], 0.f);
                float a1 = fmaxf(bv.y + wxp[h + 1], 0.f);
                uint32_t lo;
                uint32_t hi = pack_hi_lo(a0, a1, lo);
                uint32_t off = (uint32_t)row * (A_PITCH * 2) + (uint32_t)c * 4;
                *(uint32_t*)(smem + SB_A_HI + off) = hi;
                *(uint32_t*)(smem + SB_A_LO + off) = lo;
            }
            // ---- copy B tile (pre-converted bf16 hi/lo), rows o, cols k
            {
                const char* srcH = (const char*)g_Bhi + (size_t)(oc * O_CH) * 800 + kc * 160;
                const char* srcL = (const char*)g_Blo + (size_t)(oc * O_CH) * 800 + kc * 160;
                for (int t = tid; t < O_CH * 10; t += 256) {
                    int row = t / 10, q = t - row * 10;
                    uint32_t off = (uint32_t)row * (B_PITCH * 2) + (uint32_t)q * 16;
                    *(uint4*)(smem + SB_B_HI + off) = *(const uint4*)(srcH + (size_t)row * 800 + q * 16);
                    *(uint4*)(smem + SB_B_LO + off) = *(const uint4*)(srcL + (size_t)row * 800 + q * 16);
                }
            }
            __syncthreads();

#pragma unroll
            for (int ks = 0; ks < KSTEPS; ks++) {
                uint32_t ah[2][4], al[2][4];
#pragma unroll
                for (int mi = 0; mi < 2; mi++) {
                    uint32_t base = aAddr + (uint32_t)mi * (16 * A_PITCH * 2) + (uint32_t)ks * 32;
                    ldsm_x4(ah[mi], base);
                    ldsm_x4(al[mi], base + (SB_A_LO - SB_A_HI));
                }
#pragma unroll
                for (int nf = 0; nf < 7; nf++) {
                    uint32_t bb = bAddr + (uint32_t)nf * (8 * B_PITCH * 2) + (uint32_t)ks * 32;
                    uint32_t bh[2], bl[2];
                    ldsm_x2(bh, bb);
                    ldsm_x2(bl, bb + (SB_B_LO - SB_B_HI));
#pragma unroll
                    for (int mi = 0; mi < 2; mi++) {
                        mma_bf16(acc[mi][nf], ah[mi], bh);
                        mma_bf16(acc[mi][nf], ah[mi], bl);
                        mma_bf16(acc[mi][nf], al[mi], bh);
                    }
                }
            }
            __syncthreads();
        }

        // ---- epilogue for this o-chunk: + dec_b, sigmoid-BCE vs y ----
        int colBase = oc * O_CH + cg * 56 + 2 * (lane & 3);
        int rowBase = n0 + m0 + (lane >> 2);
#pragma unroll
        for (int mi = 0; mi < 2; mi++) {
            int r0 = rowBase + mi * 16;
#pragma unroll
            for (int nf = 0; nf < 7; nf++) {
                int col = colBase + nf * 8;
                float2 db = *(const float2*)&dec_b[col];
                float2 y0 = *(const float2*)&y_flat[(size_t)r0 * DY + col];
                float2 y1 = *(const float2*)&y_flat[(size_t)(r0 + 8) * DY + col];
                rec[mi * 2 + 0] += bce_term(acc[mi][nf][0] + db.x, y0.x)
                                 + bce_term(acc[mi][nf][1] + db.y, y0.y);
                rec[mi * 2 + 1] += bce_term(acc[mi][nf][2] + db.x, y1.x)
                                 + bce_term(acc[mi][nf][3] + db.y, y1.y);
            }
        }
    }

    // reduce over the 4 lanes of each quad (columns)
#pragma unroll
    for (int i = 0; i < 4; i++) {
        rec[i] += __shfl_xor_sync(0xffffffffu, rec[i], 1);
        rec[i] += __shfl_xor_sync(0xffffffffu, rec[i], 2);
    }
    float* part = (float*)(smem + SB_PART);
    if ((lane & 3) == 0) {
        int q = lane >> 2;
#pragma unroll
        for (int mi = 0; mi < 2; mi++) {
            part[cg * 128 + m0 + mi * 16 + q]     = rec[mi * 2 + 0];
            part[cg * 128 + m0 + mi * 16 + 8 + q] = rec[mi * 2 + 1];
        }
    }
    __syncthreads();
    if (tid < 128)
        g_logb[(n0 + tid) * KS + k] = -(part[tid] + part[128 + tid]) * 0.01f;
}

// ---------------- HMM forward-backward + gamma/xi ----------------------------
__global__ void hmm_kernel(const float* __restrict__ log_pi, const float* __restrict__ log_A,
                           float* __restrict__ out) {
    __shared__ float lA[16][17];
    __shared__ float lp[16];
    __shared__ float lb[TT][16];
    __shared__ float al[TT][16];
    __shared__ float be[TT][16];
    __shared__ float s_llik;
    int b = blockIdx.x;
    int tid = threadIdx.x;

    for (int e = tid; e < TT * 16; e += 256) ((float*)lb)[e] = g_logb[b * (TT * 16) + e];

    if (tid < 16) {
        int j = tid;
        float x[16], m = -1e30f;
#pragma unroll
        for (int k2 = 0; k2 < 16; k2++) { x[k2] = log_A[j * 16 + k2]; m = fmaxf(m, x[k2]); }
        float s = 0.f;
#pragma unroll
        for (int k2 = 0; k2 < 16; k2++) s += expf(x[k2] - m);
        float inv = 1.f / s;
#pragma unroll
        for (int k2 = 0; k2 < 16; k2++) lA[j][k2] = logf(expf(x[k2] - m) * inv + 1e-9f);
    } else if (tid == 16) {
        float x[16], m = -1e30f;
#pragma unroll
        for (int k2 = 0; k2 < 16; k2++) { x[k2] = log_pi[k2]; m = fmaxf(m, x[k2]); }
        float s = 0.f;
#pragma unroll
        for (int k2 = 0; k2 < 16; k2++) s += expf(x[k2] - m);
        float inv = 1.f / s;
#pragma unroll
        for (int k2 = 0; k2 < 16; k2++) lp[k2] = logf(expf(x[k2] - m) * inv + 1e-9f);
    }
    __syncthreads();

    int warp = tid >> 5, lane = tid & 31;
    if (warp == 0 && lane < 16) {
        int k = lane;
        al[0][k] = lp[k] + lb[0][k];
        __syncwarp(0xffffu);
        for (int t = 1; t < TT; t++) {
            float m = -1e30f;
#pragma unroll
            for (int j = 0; j < 16; j++) m = fmaxf(m, al[t - 1][j] + lA[j][k]);
            float s = 0.f;
#pragma unroll
            for (int j = 0; j < 16; j++) s += expf(al[t - 1][j] + lA[j][k] - m);
            al[t][k] = m + logf(s) + lb[t][k];
            __syncwarp(0xffffu);
        }
        float v = al[TT - 1][k];
        float mm = v;
#pragma unroll
        for (int off = 8; off > 0; off >>= 1) mm = fmaxf(mm, __shfl_xor_sync(0xffffu, mm, off, 16));
        float se = expf(v - mm);
#pragma unroll
        for (int off = 8; off > 0; off >>= 1) se += __shfl_xor_sync(0xffffu, se, off, 16);
        if (k == 0) s_llik = mm + logf(se);
    } else if (warp == 1 && lane < 16) {
        int j = lane;
        be[TT - 1][j] = 0.f;
        __syncwarp(0xffffu);
        for (int t = TT - 2; t >= 0; t--) {
            float m = -1e30f;
#pragma unroll
            for (int k2 = 0; k2 < 16; k2++)
                m = fmaxf(m, lA[j][k2] + lb[t + 1][k2] + be[t + 1][k2]);
            float s = 0.f;
#pragma unroll
            for (int k2 = 0; k2 < 16; k2++)
                s += expf(lA[j][k2] + lb[t + 1][k2] + be[t + 1][k2] - m);
            be[t][j] = m + logf(s);
            __syncwarp(0xffffu);
        }
    }
    __syncthreads();
    float llik = s_llik;

    float* outg = out + b * (TT * 16);
    for (int e = tid; e < TT * 16; e += 256) {
        int t = e >> 4, k = e & 15;
        outg[e] = expf(al[t][k] + be[t][k] - llik);
    }
    float* outx = out + BBAT * TT * 16 + (long)b * (TT - 1) * 256;
    int j = tid >> 4, k = tid & 15;
    float lajk = lA[j][k];
    for (int t = 0; t < TT - 1; t++) {
        float v = al[t][j] + lajk + lb[t + 1][k] + be[t + 1][k] - llik;
        outx[t * 256 + tid] = expf(v);
    }
}

// ---------------- launch -----------------------------------------------------
extern "C" void kernel_launch(void* const* d_in, const int* in_sizes, int n_in,
                              void* d_out, int out_size) {
    const float* y_batch  = (const float*)d_in[0];
    const float* enc_w1   = (const float*)d_in[1];
    const float* enc_b1   = (const float*)d_in[2];
    const float* enc_w2   = (const float*)d_in[3];
    const float* enc_b2   = (const float*)d_in[4];
    const float* dec_fc_w = (const float*)d_in[5];
    const float* dec_fc_b = (const float*)d_in[6];
    const float* dec_w    = (const float*)d_in[7];
    const float* dec_b    = (const float*)d_in[8];
    const float* log_pi   = (const float*)d_in[9];
    const float* log_A    = (const float*)d_in[10];
    const float* eps      = (const float*)d_in[11];
    float* out = (float*)d_out;

    static int configured = 0;
    if (!configured) {
        cudaFuncSetAttribute(bk_mma_kernel, cudaFuncAttributeMaxDynamicSharedMemorySize, SMEM_BK);
        configured = 1;
    }

    dim3 tb(32, 8);
    transpose_kernel<<<dim3((DY + 31) / 32, (NR + 31) / 32), tb>>>(y_batch, NR, DY, 0);
    transpose_kernel<<<dim3((DY + 31) / 32, (DH + 31) / 32), tb>>>(enc_w1, DH, DY, 1);
    b_prep_kernel<<<(DY * 200 + 255) / 256, 256>>>(dec_w);

    gemm1_kernel<<<dim3(NR / 64, (DH + 63) / 64), 256>>>(enc_b1);
    enc2_kernel<<<NR / 16, 256>>>(enc_w2, enc_b2, eps);
    dec_base_kernel<<<(DH * NR) / 256, 256>>>(dec_fc_w, dec_fc_b);
    bk_mma_kernel<<<dim3(NR / M_TILE, KS), 256, SMEM_BK>>>(dec_fc_w, dec_b, y_batch);
    hmm_kernel<<<BBAT, 256>>>(log_pi, log_A, out);
}